// round 9
// baseline (speedup 1.0000x reference)
#include <cuda_runtime.h>
#include <cuda_fp16.h>
#include <cstdint>

#define BB 4
#define CC 256
#define OO 256
#define HH 192
#define WW 192
#define HWP (HH*WW)          // 36864
#define KK 2304              // 9 taps * 256 ch
#define MT 64                // pixels per CTA tile
#define NCHUNK 36

// ---- scratch (__device__ globals: allocation-free) ----
__device__ __align__(16) __half g_xn[(size_t)BB*HWP*CC];   // NHWC x, fp16
__device__ float g_sx[BB*HWP];
__device__ float g_sy[BB*HWP];
__device__ __align__(16) __half g_wh[OO*KK];               // weight fp16, [o][t*256+c]
__device__ __align__(16) __half g_spwh[2*9*256];           // sp weights fp16 [ch][tap][c]

// ================= helpers (plain sm_80+ PTX only) =================
__device__ __forceinline__ uint32_t s2u(const void* p) {
    uint32_t a;
    asm("{ .reg .u64 t; cvta.to.shared.u64 t, %1; cvt.u32.u64 %0, t; }" : "=r"(a) : "l"(p));
    return a;
}
__device__ __forceinline__ uint32_t hpack(float lo, float hi) {
    uint32_t r;
    asm("cvt.rn.f16x2.f32 %0, %1, %2;" : "=r"(r) : "f"(hi), "f"(lo));
    return r;
}
__device__ __forceinline__ float2 h2f(uint32_t u) {
    __half2 h = *reinterpret_cast<__half2*>(&u);
    return __half22float2(h);
}
__device__ __forceinline__ void sts128u(uint32_t a, uint32_t x, uint32_t y, uint32_t z, uint32_t w) {
    asm volatile("st.shared.v4.b32 [%0], {%1, %2, %3, %4};"
                 :: "r"(a), "r"(x), "r"(y), "r"(z), "r"(w) : "memory");
}
__device__ __forceinline__ void ldm4(uint32_t* r, uint32_t a) {
    asm volatile("ldmatrix.sync.aligned.m8n8.x4.shared.b16 {%0,%1,%2,%3}, [%4];"
                 : "=r"(r[0]), "=r"(r[1]), "=r"(r[2]), "=r"(r[3]) : "r"(a));
}
__device__ __forceinline__ void mma16816(float* d, const uint32_t* a, uint32_t b0, uint32_t b1) {
    asm volatile("mma.sync.aligned.m16n8k16.row.col.f32.f16.f16.f32 "
                 "{%0,%1,%2,%3}, {%4,%5,%6,%7}, {%8,%9}, {%0,%1,%2,%3};"
                 : "+f"(d[0]), "+f"(d[1]), "+f"(d[2]), "+f"(d[3])
                 : "r"(a[0]), "r"(a[1]), "r"(a[2]), "r"(a[3]), "r"(b0), "r"(b1));
}
__device__ __forceinline__ void cpasync16(uint32_t dst, const void* src) {
    asm volatile("cp.async.cg.shared.global [%0], [%1], 16;"
                 :: "r"(dst), "l"(__cvta_generic_to_global(src)) : "memory");
}

// k_main smem layout (bytes)
#define OFF_A(s)   ((s)*8192)          // A: 2 x 64 rows x 128B (XOR-swizzled)
#define OFF_B(s)   (16384 + (s)*32768) // B: 2 x 256 rows x 128B (XOR-swizzled)
#define SMEM_DYN   81920

// ============ K1: NCHW -> NHWC fp16 transpose (vectorized both sides) ============
// block 256 thr: tile 64 c x 64 hw. Load float4 rows, store uint4 (8 fp16 ch).
__global__ __launch_bounds__(256)
void k_transpose(const float* __restrict__ x) {
    __shared__ float tile[64*65];
    int hw0 = blockIdx.x * 64, c0 = blockIdx.y * 64, b = blockIdx.z;
    int tid = threadIdx.x;
    // load: 64 c-rows x 64 hw; 4 threads per row, each 4x float4
    {
        int r = tid >> 2;            // c row 0..63
        int h4 = (tid & 3) * 16;     // hw offset
        const float* src = x + ((size_t)(b*CC + c0 + r))*HWP + hw0 + h4;
        float* dst = tile + r*65 + h4;
#pragma unroll
        for (int i = 0; i < 4; ++i) {
            float4 v = *(const float4*)(src + i*4);
            dst[i*4+0] = v.x; dst[i*4+1] = v.y; dst[i*4+2] = v.z; dst[i*4+3] = v.w;
        }
    }
    __syncthreads();
    // store: each thread: 2 hw rows x 8 channels -> uint4
    {
        int cg = tid & 7;            // channel group of 8
        int hw = tid >> 3;           // 0..31
#pragma unroll
        for (int i = 0; i < 2; ++i) {
            int h = hw + i*32;
            uint32_t rr[4];
#pragma unroll
            for (int q = 0; q < 4; ++q) {
                float f0 = tile[(cg*8 + q*2 + 0)*65 + h];
                float f1 = tile[(cg*8 + q*2 + 1)*65 + h];
                rr[q] = hpack(f0, f1);
            }
            *(uint4*)(g_xn + ((size_t)b*HWP + hw0 + h)*CC + c0 + cg*8) =
                make_uint4(rr[0], rr[1], rr[2], rr[3]);
        }
    }
}

// ============ K2: weight -> fp16 [o][t*256+c] ============
__global__ void k_whalf(const float* __restrict__ w) {
    int idx = blockIdx.x*256 + threadIdx.x;
    int o = idx / KK, k = idx - o*KK;
    int t = k >> 8, c = k & 255;
    g_wh[idx] = __float2half_rn(w[(o*CC + c)*9 + t]);
}

// ============ K2b: sp weight -> fp16 [ch][tap][c] ============
__global__ void k_spwt(const float* __restrict__ spw) {
    int i = blockIdx.x*256 + threadIdx.x;
    if (i >= 2*9*256) return;
    int ch = i / 2304, rem = i - ch*2304;
    int t = rem >> 8, c = rem & 255;
    g_spwh[i] = __float2half_rn(spw[(ch*CC + c)*9 + t]);
}

// ============ K3: scale-predictor conv, smem-tiled, 16-ch chunks ============
__global__ __launch_bounds__(256)
void k_spconv(const float* __restrict__ spb) {
    __shared__ __align__(16) __half ws[2*9*256];   // 9216 B
    __shared__ uint4 xs[648];                      // 10368 B: 18x18 px x 16ch fp16
    int tid = threadIdx.x;
    for (int i = tid; i < 576; i += 256)
        ((uint4*)ws)[i] = ((const uint4*)g_spwh)[i];

    int bx = blockIdx.x % (WW/16), rem = blockIdx.x / (WW/16);
    int by = rem % (HH/16), b = rem / (HH/16);
    int x0 = bx*16, y0 = by*16;
    int tx = tid & 15, ty = tid >> 4;

    float a0 = 0.f, a1 = 0.f;
    for (int cc = 0; cc < 16; ++cc) {
        __syncthreads();
        for (int tau = tid; tau < 648; tau += 256) {
            int pix = tau >> 1, half = tau & 1;
            int py = pix / 18, px = pix - py*18;
            int gy = y0 + py - 1, gx = x0 + px - 1;
            uint4 v = make_uint4(0u, 0u, 0u, 0u);
            if (gy >= 0 && gy < HH && gx >= 0 && gx < WW)
                v = *(const uint4*)(g_xn + ((size_t)b*HWP + gy*WW + gx)*CC + cc*16 + half*8);
            xs[tau] = v;
        }
        __syncthreads();
#pragma unroll
        for (int t = 0; t < 9; ++t) {
            int pix = (ty + t/3)*18 + tx + t%3;
#pragma unroll
            for (int half = 0; half < 2; ++half) {
                uint4 xv = xs[pix*2 + half];
                uint4 wa = *(const uint4*)(ws + t*256 + cc*16 + half*8);
                uint4 wb = *(const uint4*)(ws + 2304 + t*256 + cc*16 + half*8);
                const uint32_t* xw = &xv.x;
                const uint32_t* aw = &wa.x;
                const uint32_t* bw = &wb.x;
#pragma unroll
                for (int q = 0; q < 4; ++q) {
                    float2 xf = h2f(xw[q]);
                    float2 af = h2f(aw[q]);
                    float2 bf = h2f(bw[q]);
                    a0 += xf.x*af.x + xf.y*af.y;
                    a1 += xf.x*bf.x + xf.y*bf.y;
                }
            }
        }
    }
    int p = (b*HH + y0+ty)*WW + x0+tx;
    g_sx[p] = expf(fminf(fmaxf(a0 + spb[0], -2.f), 2.f));
    g_sy[p] = expf(fminf(fmaxf(a1 + spb[1], -2.f), 2.f));
}

// ============ K4: main — fp16 gather + single-term fp16 HMMA, 2 CTAs/SM ============
// 256 threads = 8 warps (2M x 4N). Coords in registers (fixed pixel pair/thread).
__global__ void __launch_bounds__(256, 2)
k_main(const float* __restrict__ bias, float* __restrict__ out) {
    extern __shared__ char sm[];
    const uint32_t SMB = s2u(sm);

    const int tid  = threadIdx.x;
    const int wid  = tid >> 5, lane = tid & 31;
    const int wm   = wid & 1;          // M group (32 rows)
    const int wn   = wid >> 1;         // N group (64 cols)
    const int m0 = blockIdx.x * MT;
    const int b  = m0 / HWP;
    const int pb = b * HWP;
    const int p0 = m0 - pb;
    const int phase = ((blockIdx.x >> 2) & 1) * 16;

    // this thread's two gather pixels (fixed across all chunks)
    const int q1 = tid >> 3;           // 0..31
    const int jj = tid & 7;            // channel group of 8
    int py1, px1, py2, px2;
    {
        int r1 = p0 + q1;      py1 = r1 / WW; px1 = r1 - py1*WW;
        int r2 = p0 + q1 + 32; py2 = r2 / WW; px2 = r2 - py2*WW;
    }
    const float sx1 = g_sx[pb + py1*WW + px1], sy1 = g_sy[pb + py1*WW + px1];
    const float sx2 = g_sx[pb + py2*WW + px2], sy2 = g_sy[pb + py2*WW + px2];
    int   o1 = 0, d1x = 0, d1y = 0;  float w1x = 0.f, w1y = 0.f;
    int   o2 = 0, d2x = 0, d2y = 0;  float w2x = 0.f, w2y = 0.f;

    // ldmatrix lane addressing (A and B both 128B-row XOR-swizzled)
    const int lrow = lane & 7;
    const int a_row16 = lrow + ((lane >> 3) & 1) * 8;
    const uint32_t arow0 = (uint32_t)(wm*32 + a_row16) * 128u;
    const uint32_t axor  = (uint32_t)lrow << 4;
    const uint32_t akk   = (uint32_t)(lane >> 4) * 16u;
    const int b_n   = (lane >> 4) * 8 + lrow;
    const int brow  = wn*64 + b_n;
    const uint32_t bbase = (uint32_t)brow * 128u;
    const uint32_t bxor  = ((uint32_t)brow & 7u) << 4;
    const uint32_t bkk   = ((lane >> 3) & 1) * 16u;

    float acc[2][8][4];
#pragma unroll
    for (int i = 0; i < 2; ++i)
#pragma unroll
        for (int j = 0; j < 8; ++j)
#pragma unroll
            for (int q = 0; q < 4; ++q) acc[i][j][q] = 0.f;

    // ---- prologue: prefetch B(first chunk) ----
    {
        const int kc0 = phase % NCHUNK;
        const uint32_t BD = SMB + OFF_B(0);
#pragma unroll
        for (int it = 0; it < 8; ++it) {
            int tau = tid + it*256;
            int r = tau >> 3, u = tau & 7;
            uint32_t off = (uint32_t)(r*128 + u*16);
            cpasync16(BD + (off ^ ((off >> 3) & 0x70u)),
                      g_wh + (size_t)r*KK + kc0*64 + u*8);
        }
        asm volatile("cp.async.commit_group;" ::: "memory");
    }

    for (int ic = 0; ic < NCHUNK; ++ic) {
        const int s = ic & 1;
        const int kc = (ic + phase) % NCHUNK;
        const int t = kc >> 2;
        const int cbase = (kc & 3) * 64;

        if ((kc & 3) == 0) {     // new tap: per-thread register coords
            float cx = (float)(t % 3 - 1), cy = (float)(t / 3 - 1);
            {
                float gx = fminf(fmaxf((float)px1 + cx*sx1, 0.f), (float)(WW-1));
                float gy = fminf(fmaxf((float)py1 + cy*sy1, 0.f), (float)(HH-1));
                float x0f = floorf(gx), y0f = floorf(gy);
                w1x = gx - x0f; w1y = gy - y0f;
                int ix0 = (int)x0f, iy0 = (int)y0f;
                o1  = (pb + iy0*WW + ix0) * CC;
                d1x = (ix0 + 1 < WW) ? CC : 0;
                d1y = (iy0 + 1 < HH) ? WW*CC : 0;
            }
            {
                float gx = fminf(fmaxf((float)px2 + cx*sx2, 0.f), (float)(WW-1));
                float gy = fminf(fmaxf((float)py2 + cy*sy2, 0.f), (float)(HH-1));
                float x0f = floorf(gx), y0f = floorf(gy);
                w2x = gx - x0f; w2y = gy - y0f;
                int ix0 = (int)x0f, iy0 = (int)y0f;
                o2  = (pb + iy0*WW + ix0) * CC;
                d2x = (ix0 + 1 < WW) ? CC : 0;
                d2y = (iy0 + 1 < HH) ? WW*CC : 0;
            }
        }

        __syncthreads();   // prev MMA done: A[s] and B[s^1] free

        // ---- prefetch B(next chunk) into the other buffer ----
        if (ic + 1 < NCHUNK) {
            const int kcn = (ic + 1 + phase) % NCHUNK;
            const uint32_t BD = SMB + OFF_B(s ^ 1);
#pragma unroll
            for (int it = 0; it < 8; ++it) {
                int tau = tid + it*256;
                int r = tau >> 3, u = tau & 7;
                uint32_t off = (uint32_t)(r*128 + u*16);
                cpasync16(BD + (off ^ ((off >> 3) & 0x70u)),
                          g_wh + (size_t)r*KK + kcn*64 + u*8);
            }
            asm volatile("cp.async.commit_group;" ::: "memory");
        }

        // ---- A gather: 2 fixed pixels x 8 ch fp16 each -> swizzled tile ----
        const uint32_t AT = SMB + OFF_A(s);
        const int cb = cbase + jj*8;
#pragma unroll
        for (int pp = 0; pp < 2; ++pp) {
            const int  ob  = pp ? o2 : o1;
            const int  dx  = pp ? d2x : d1x;
            const int  dy  = pp ? d2y : d1y;
            const float wx = pp ? w2x : w1x;
            const float wy = pp ? w2y : w1y;
            const int p = q1 + pp*32;
            uint4 u00 = *(const uint4*)(g_xn + (size_t)(ob)           + cb);
            uint4 u01 = *(const uint4*)(g_xn + (size_t)(ob + dx)      + cb);
            uint4 u10 = *(const uint4*)(g_xn + (size_t)(ob + dy)      + cb);
            uint4 u11 = *(const uint4*)(g_xn + (size_t)(ob + dx + dy) + cb);
            float w00 = (1.f-wx)*(1.f-wy), w01 = wx*(1.f-wy);
            float w10 = (1.f-wx)*wy,       w11 = wx*wy;
            const uint32_t* a  = &u00.x;
            const uint32_t* bb = &u01.x;
            const uint32_t* c  = &u10.x;
            const uint32_t* d  = &u11.x;
            uint32_t rr[4];
#pragma unroll
            for (int q = 0; q < 4; ++q) {
                float2 f00 = h2f(a[q]), f01 = h2f(bb[q]);
                float2 f10 = h2f(c[q]), f11 = h2f(d[q]);
                float g0 = w00*f00.x + w01*f01.x + w10*f10.x + w11*f11.x;
                float g1 = w00*f00.y + w01*f01.y + w10*f10.y + w11*f11.y;
                rr[q] = hpack(g0, g1);
            }
            uint32_t off = (uint32_t)(p*128 + jj*16);
            sts128u(AT + (off ^ ((off >> 3) & 0x70u)), rr[0], rr[1], rr[2], rr[3]);
        }

        if (ic + 1 < NCHUNK) {
            asm volatile("cp.async.wait_group 1;" ::: "memory");   // B(ic) ready
        } else {
            asm volatile("cp.async.wait_group 0;" ::: "memory");
        }
        __syncthreads();

        // ---- MMA: 4 k16 steps, single fp16 term ----
        const uint32_t BH = SMB + OFF_B(s);
#pragma unroll
        for (int ks = 0; ks < 4; ++ks) {
            uint32_t a0[4], a1[4];
            uint32_t ka = ((uint32_t)(ks*32) + akk) ^ axor;
            ldm4(a0, AT + arow0 + ka);
            ldm4(a1, AT + arow0 + 2048 + ka);
            uint32_t kb = ((uint32_t)(ks*32) + bkk) ^ bxor;
#pragma unroll
            for (int nt = 0; nt < 4; ++nt) {
                uint32_t bh[4];
                ldm4(bh, BH + bbase + nt*2048 + kb);
                int n0 = nt*2;
                mma16816(acc[0][n0],   a0, bh[0], bh[1]);
                mma16816(acc[0][n0+1], a0, bh[2], bh[3]);
                mma16816(acc[1][n0],   a1, bh[0], bh[1]);
                mma16816(acc[1][n0+1], a1, bh[2], bh[3]);
            }
        }
    }

    // ---- epilogue: stage 256 o x 64 px through smem (stride 68) ----
    __syncthreads();
    float* ep = (float*)sm;
    const int qrow = lane >> 2;
    const int qcol = (lane & 3) * 2;
#pragma unroll
    for (int mt = 0; mt < 2; ++mt) {
#pragma unroll
        for (int nn = 0; nn < 8; ++nn) {
            int ol = wn*64 + nn*8 + qcol;
            int pr = wm*32 + mt*16 + qrow;
            ep[ol*68 + pr]         = acc[mt][nn][0];
            ep[(ol+1)*68 + pr]     = acc[mt][nn][1];
            ep[ol*68 + pr + 8]     = acc[mt][nn][2];
            ep[(ol+1)*68 + pr + 8] = acc[mt][nn][3];
        }
    }
    __syncthreads();
#pragma unroll
    for (int i = 0; i < 16; ++i) {
        int o = i*16 + (tid >> 4);
        int q = tid & 15;
        float bv = __ldg(&bias[o]);
        const float* er = ep + o*68 + q*4;
        float4 v = make_float4(er[0]+bv, er[1]+bv, er[2]+bv, er[3]+bv);
        *(float4*)(out + ((size_t)(b*OO + o))*HWP + p0 + q*4) = v;
    }
}

extern "C" void kernel_launch(void* const* d_in, const int* in_sizes, int n_in,
                              void* d_out, int out_size) {
    const float* x    = (const float*)d_in[0];
    const float* w    = (const float*)d_in[1];
    const float* bias = (const float*)d_in[2];
    const float* spw  = (const float*)d_in[3];
    const float* spb  = (const float*)d_in[4];
    float* out = (float*)d_out;

    cudaFuncSetAttribute(k_main, cudaFuncAttributeMaxDynamicSharedMemorySize, SMEM_DYN);

    k_transpose<<<dim3(HWP/64, CC/64, BB), 256>>>(x);
    k_whalf   <<<(OO*KK)/256, 256>>>(w);
    k_spwt    <<<(2*9*256 + 255)/256, 256>>>(spw);
    k_spconv  <<<BB*(HH/16)*(WW/16), 256>>>(spb);
    k_main    <<<(BB*HWP)/MT, 256, SMEM_DYN>>>(bias, out);
}

// round 10
// speedup vs baseline: 1.0093x; 1.0093x over previous
#include <cuda_runtime.h>
#include <cuda_fp16.h>
#include <cstdint>

#define BB 4
#define CC 256
#define OO 256
#define HH 192
#define WW 192
#define HWP (HH*WW)          // 36864
#define KK 2304              // 9 taps * 256 ch
#define MT 64                // pixels per CTA tile
#define NCHUNK 36

// ---- scratch (__device__ globals: allocation-free) ----
__device__ __align__(16) __half g_xn[(size_t)BB*HWP*CC];   // NHWC x, fp16
__device__ float g_sx[BB*HWP];
__device__ float g_sy[BB*HWP];
__device__ __align__(16) __half g_wh[OO*KK];               // weight fp16, [o][t*256+c]
__device__ __align__(16) float g_spwt[2*9*256];            // sp weights fp32 [ch][tap][c]

// ================= helpers (plain sm_80+ PTX only) =================
__device__ __forceinline__ uint32_t s2u(const void* p) {
    uint32_t a;
    asm("{ .reg .u64 t; cvta.to.shared.u64 t, %1; cvt.u32.u64 %0, t; }" : "=r"(a) : "l"(p));
    return a;
}
__device__ __forceinline__ uint32_t hpack(float lo, float hi) {
    uint32_t r;
    asm("cvt.rn.f16x2.f32 %0, %1, %2;" : "=r"(r) : "f"(hi), "f"(lo));
    return r;
}
__device__ __forceinline__ float2 h2f(uint32_t u) {
    __half2 h = *reinterpret_cast<__half2*>(&u);
    return __half22float2(h);
}
__device__ __forceinline__ void sts128u(uint32_t a, uint32_t x, uint32_t y, uint32_t z, uint32_t w) {
    asm volatile("st.shared.v4.b32 [%0], {%1, %2, %3, %4};"
                 :: "r"(a), "r"(x), "r"(y), "r"(z), "r"(w) : "memory");
}
__device__ __forceinline__ void ldm4(uint32_t* r, uint32_t a) {
    asm volatile("ldmatrix.sync.aligned.m8n8.x4.shared.b16 {%0,%1,%2,%3}, [%4];"
                 : "=r"(r[0]), "=r"(r[1]), "=r"(r[2]), "=r"(r[3]) : "r"(a));
}
__device__ __forceinline__ void mma16816(float* d, const uint32_t* a, uint32_t b0, uint32_t b1) {
    asm volatile("mma.sync.aligned.m16n8k16.row.col.f32.f16.f16.f32 "
                 "{%0,%1,%2,%3}, {%4,%5,%6,%7}, {%8,%9}, {%0,%1,%2,%3};"
                 : "+f"(d[0]), "+f"(d[1]), "+f"(d[2]), "+f"(d[3])
                 : "r"(a[0]), "r"(a[1]), "r"(a[2]), "r"(a[3]), "r"(b0), "r"(b1));
}
__device__ __forceinline__ void cpasync16(uint32_t dst, const void* src) {
    asm volatile("cp.async.cg.shared.global [%0], [%1], 16;"
                 :: "r"(dst), "l"(__cvta_generic_to_global(src)) : "memory");
}

// k_main smem layout (bytes)
#define OFF_A(s)   ((s)*8192)          // A: 2 x 64 rows x 128B (XOR-swizzled)
#define OFF_B(s)   (16384 + (s)*32768) // B: 2 x 256 rows x 128B (XOR-swizzled)
#define SMEM_DYN   81920

// ============ K1: NCHW -> NHWC fp16 transpose (vectorized both sides) ============
__global__ __launch_bounds__(256)
void k_transpose(const float* __restrict__ x) {
    __shared__ float tile[64*65];
    int hw0 = blockIdx.x * 64, c0 = blockIdx.y * 64, b = blockIdx.z;
    int tid = threadIdx.x;
    {
        int r = tid >> 2;
        int h4 = (tid & 3) * 16;
        const float* src = x + ((size_t)(b*CC + c0 + r))*HWP + hw0 + h4;
        float* dst = tile + r*65 + h4;
#pragma unroll
        for (int i = 0; i < 4; ++i) {
            float4 v = *(const float4*)(src + i*4);
            dst[i*4+0] = v.x; dst[i*4+1] = v.y; dst[i*4+2] = v.z; dst[i*4+3] = v.w;
        }
    }
    __syncthreads();
    {
        int cg = tid & 7;
        int hw = tid >> 3;
#pragma unroll
        for (int i = 0; i < 2; ++i) {
            int h = hw + i*32;
            uint32_t rr[4];
#pragma unroll
            for (int q = 0; q < 4; ++q) {
                float f0 = tile[(cg*8 + q*2 + 0)*65 + h];
                float f1 = tile[(cg*8 + q*2 + 1)*65 + h];
                rr[q] = hpack(f0, f1);
            }
            *(uint4*)(g_xn + ((size_t)b*HWP + hw0 + h)*CC + c0 + cg*8) =
                make_uint4(rr[0], rr[1], rr[2], rr[3]);
        }
    }
}

// ============ K2: weight -> fp16 [o][t*256+c] ============
__global__ void k_whalf(const float* __restrict__ w) {
    int idx = blockIdx.x*256 + threadIdx.x;
    int o = idx / KK, k = idx - o*KK;
    int t = k >> 8, c = k & 255;
    g_wh[idx] = __float2half_rn(w[(o*CC + c)*9 + t]);
}

// ============ K2b: sp weight -> fp32 [ch][tap][c] ============
__global__ void k_spwt(const float* __restrict__ spw) {
    int i = blockIdx.x*256 + threadIdx.x;
    if (i >= 2*9*256) return;
    int ch = i / 2304, rem = i - ch*2304;
    int t = rem >> 8, c = rem & 255;
    g_spwt[i] = spw[(ch*CC + c)*9 + t];
}

// ============ K3: scale-predictor conv, smem-tiled (fp16 x, fp32 w) ============
__global__ __launch_bounds__(256)
void k_spconv(const float* __restrict__ spb) {
    __shared__ __align__(16) float ws[2*9*256];    // 18432 B
    __shared__ uint4 xs[648];                      // 10368 B: 18x18 px x 16ch fp16
    int tid = threadIdx.x;
    for (int i = tid; i < 1152; i += 256)
        ((float4*)ws)[i] = ((const float4*)g_spwt)[i];

    int bx = blockIdx.x % (WW/16), rem = blockIdx.x / (WW/16);
    int by = rem % (HH/16), b = rem / (HH/16);
    int x0 = bx*16, y0 = by*16;
    int tx = tid & 15, ty = tid >> 4;

    float a0 = 0.f, a1 = 0.f;
    for (int cc = 0; cc < 16; ++cc) {
        __syncthreads();
        for (int tau = tid; tau < 648; tau += 256) {
            int pix = tau >> 1, half = tau & 1;
            int py = pix / 18, px = pix - py*18;
            int gy = y0 + py - 1, gx = x0 + px - 1;
            uint4 v = make_uint4(0u, 0u, 0u, 0u);
            if (gy >= 0 && gy < HH && gx >= 0 && gx < WW)
                v = *(const uint4*)(g_xn + ((size_t)b*HWP + gy*WW + gx)*CC + cc*16 + half*8);
            xs[tau] = v;
        }
        __syncthreads();
#pragma unroll
        for (int t = 0; t < 9; ++t) {
            int pix = (ty + t/3)*18 + tx + t%3;
#pragma unroll
            for (int half = 0; half < 2; ++half) {
                uint4 xv = xs[pix*2 + half];
                const float* w0 = ws + t*256 + cc*16 + half*8;
                const float* w1 = ws + 2304 + t*256 + cc*16 + half*8;
                const uint32_t* xw = &xv.x;
#pragma unroll
                for (int q = 0; q < 4; ++q) {
                    float2 xf = h2f(xw[q]);
                    a0 += xf.x*w0[q*2] + xf.y*w0[q*2+1];
                    a1 += xf.x*w1[q*2] + xf.y*w1[q*2+1];
                }
            }
        }
    }
    int p = (b*HH + y0+ty)*WW + x0+tx;
    g_sx[p] = expf(fminf(fmaxf(a0 + spb[0], -2.f), 2.f));
    g_sy[p] = expf(fminf(fmaxf(a1 + spb[1], -2.f), 2.f));
}

// ============ K4: main — pipelined gather-in-MMA, single fp16 HMMA, 2 CTAs/SM ============
// 256 threads = 8 warps (2M x 4N). One barrier/chunk; chunk ic+1's gather LDG/blend/STS
// executes inside chunk ic's MMA phase (latency hidden). A and B double-buffered.
__global__ void __launch_bounds__(256, 2)
k_main(const float* __restrict__ bias, float* __restrict__ out) {
    extern __shared__ char sm[];
    const uint32_t SMB = s2u(sm);

    const int tid  = threadIdx.x;
    const int wid  = tid >> 5, lane = tid & 31;
    const int wm   = wid & 1;
    const int wn   = wid >> 1;
    const int m0 = blockIdx.x * MT;
    const int b  = m0 / HWP;
    const int pb = b * HWP;
    const int p0 = m0 - pb;
    const int phase = ((blockIdx.x >> 2) & 1) * 16;

    // this thread's two gather pixels
    const int q1 = tid >> 3;           // 0..31
    const int jj = tid & 7;            // channel group of 8
    int py1, px1, py2, px2;
    {
        int r1 = p0 + q1;      py1 = r1 / WW; px1 = r1 - py1*WW;
        int r2 = p0 + q1 + 32; py2 = r2 / WW; px2 = r2 - py2*WW;
    }
    const float sx1 = g_sx[pb + py1*WW + px1], sy1 = g_sy[pb + py1*WW + px1];
    const float sx2 = g_sx[pb + py2*WW + px2], sy2 = g_sy[pb + py2*WW + px2];
    int   o1 = 0, d1x = 0, d1y = 0;  float w1x = 0.f, w1y = 0.f;
    int   o2 = 0, d2x = 0, d2y = 0;  float w2x = 0.f, w2y = 0.f;

    // ldmatrix lane addressing
    const int lrow = lane & 7;
    const int a_row16 = lrow + ((lane >> 3) & 1) * 8;
    const uint32_t arow0 = (uint32_t)(wm*32 + a_row16) * 128u;
    const uint32_t axor  = (uint32_t)lrow << 4;
    const uint32_t akk   = (uint32_t)(lane >> 4) * 16u;
    const int b_n   = (lane >> 4) * 8 + lrow;
    const int brow  = wn*64 + b_n;
    const uint32_t bbase = (uint32_t)brow * 128u;
    const uint32_t bxor  = ((uint32_t)brow & 7u) << 4;
    const uint32_t bkk   = ((lane >> 3) & 1) * 16u;

    float acc[2][8][4];
#pragma unroll
    for (int i = 0; i < 2; ++i)
#pragma unroll
        for (int j = 0; j < 8; ++j)
#pragma unroll
            for (int q = 0; q < 4; ++q) acc[i][j][q] = 0.f;

    // ---- coord update helper (macro to stay in registers) ----
#define COORDS(T)                                                               \
    {   float cx = (float)((T) % 3 - 1), cy = (float)((T) / 3 - 1);             \
        {   float gx = fminf(fmaxf((float)px1 + cx*sx1, 0.f), (float)(WW-1));   \
            float gy = fminf(fmaxf((float)py1 + cy*sy1, 0.f), (float)(HH-1));   \
            float x0f = floorf(gx), y0f = floorf(gy);                           \
            w1x = gx - x0f; w1y = gy - y0f;                                     \
            int ix0 = (int)x0f, iy0 = (int)y0f;                                 \
            o1  = (pb + iy0*WW + ix0) * CC;                                     \
            d1x = (ix0 + 1 < WW) ? CC : 0;                                      \
            d1y = (iy0 + 1 < HH) ? WW*CC : 0; }                                 \
        {   float gx = fminf(fmaxf((float)px2 + cx*sx2, 0.f), (float)(WW-1));   \
            float gy = fminf(fmaxf((float)py2 + cy*sy2, 0.f), (float)(HH-1));   \
            float x0f = floorf(gx), y0f = floorf(gy);                           \
            w2x = gx - x0f; w2y = gy - y0f;                                     \
            int ix0 = (int)x0f, iy0 = (int)y0f;                                 \
            o2  = (pb + iy0*WW + ix0) * CC;                                     \
            d2x = (ix0 + 1 < WW) ? CC : 0;                                      \
            d2y = (iy0 + 1 < HH) ? WW*CC : 0; } }

#define LDG4(cbj, ob, dx, dy)                                                   \
    u00 = *(const uint4*)(g_xn + (size_t)((ob))            + (cbj));            \
    u01 = *(const uint4*)(g_xn + (size_t)((ob) + (dx))      + (cbj));           \
    u10 = *(const uint4*)(g_xn + (size_t)((ob) + (dy))      + (cbj));           \
    u11 = *(const uint4*)(g_xn + (size_t)((ob) + (dx)+(dy)) + (cbj));

#define BLEND_STS(AW, prow, wx, wy)                                             \
    {   float w00 = (1.f-(wx))*(1.f-(wy)), w01 = (wx)*(1.f-(wy));               \
        float w10 = (1.f-(wx))*(wy),       w11 = (wx)*(wy);                     \
        const uint32_t* pa = &u00.x; const uint32_t* pbq = &u01.x;              \
        const uint32_t* pc = &u10.x; const uint32_t* pd = &u11.x;               \
        uint32_t rr[4];                                                         \
        _Pragma("unroll")                                                       \
        for (int q = 0; q < 4; ++q) {                                           \
            float2 f00 = h2f(pa[q]), f01 = h2f(pbq[q]);                         \
            float2 f10 = h2f(pc[q]), f11 = h2f(pd[q]);                          \
            float g0 = w00*f00.x + w01*f01.x + w10*f10.x + w11*f11.x;           \
            float g1 = w00*f00.y + w01*f01.y + w10*f10.y + w11*f11.y;           \
            rr[q] = hpack(g0, g1);                                              \
        }                                                                       \
        uint32_t off = (uint32_t)((prow)*128 + jj*16);                          \
        sts128u((AW) + (off ^ ((off >> 3) & 0x70u)), rr[0], rr[1], rr[2], rr[3]); }

#define MMA_HALF(ksbase)                                                        \
    _Pragma("unroll")                                                           \
    for (int ks = (ksbase); ks < (ksbase)+2; ++ks) {                            \
        uint32_t a0r[4], a1r[4];                                                \
        uint32_t ka = ((uint32_t)(ks*32) + akk) ^ axor;                         \
        ldm4(a0r, AT_r + arow0 + ka);                                           \
        ldm4(a1r, AT_r + arow0 + 2048 + ka);                                    \
        uint32_t kb = ((uint32_t)(ks*32) + bkk) ^ bxor;                         \
        _Pragma("unroll")                                                       \
        for (int nt = 0; nt < 4; ++nt) {                                        \
            uint32_t bh[4];                                                     \
            ldm4(bh, BH + bbase + nt*2048 + kb);                                \
            int n0 = nt*2;                                                      \
            mma16816(acc[0][n0],   a0r, bh[0], bh[1]);                          \
            mma16816(acc[0][n0+1], a0r, bh[2], bh[3]);                          \
            mma16816(acc[1][n0],   a1r, bh[0], bh[1]);                          \
            mma16816(acc[1][n0+1], a1r, bh[2], bh[3]);                          \
        }                                                                       \
    }

    // ---- prologue: cp.async B(chunk0); gather chunk0 -> A[0] directly ----
    {
        const int kc0 = phase % NCHUNK;
        const uint32_t BD = SMB + OFF_B(0);
#pragma unroll
        for (int it = 0; it < 8; ++it) {
            int tau = tid + it*256;
            int r = tau >> 3, u = tau & 7;
            uint32_t off = (uint32_t)(r*128 + u*16);
            cpasync16(BD + (off ^ ((off >> 3) & 0x70u)),
                      g_wh + (size_t)r*KK + kc0*64 + u*8);
        }
        asm volatile("cp.async.commit_group;" ::: "memory");

        COORDS(kc0 >> 2);
        const int cbj = (kc0 & 3)*64 + jj*8;
        const uint32_t AW = SMB + OFF_A(0);
        uint4 u00, u01, u10, u11;
        LDG4(cbj, o1, d1x, d1y);
        BLEND_STS(AW, q1, w1x, w1y);
        LDG4(cbj, o2, d2x, d2y);
        BLEND_STS(AW, q1 + 32, w2x, w2y);
    }

    for (int ic = 0; ic < NCHUNK; ++ic) {
        const int s = ic & 1;
        const uint32_t AT_r = SMB + OFF_A(s);
        const uint32_t AT_w = SMB + OFF_A(s ^ 1);
        const uint32_t BH   = SMB + OFF_B(s);
        const bool more = (ic + 1 < NCHUNK);

        asm volatile("cp.async.wait_group 0;" ::: "memory");   // B(ic) landed
        __syncthreads();     // A[s],B[s] ready; all warps done with MMA(ic-1)

        int cbj = 0;
        uint4 u00, u01, u10, u11;
        if (more) {
            const int kcn = (ic + 1 + phase) % NCHUNK;
            // prefetch B(ic+1)
            const uint32_t BD = SMB + OFF_B(s ^ 1);
#pragma unroll
            for (int it = 0; it < 8; ++it) {
                int tau = tid + it*256;
                int r = tau >> 3, u = tau & 7;
                uint32_t off = (uint32_t)(r*128 + u*16);
                cpasync16(BD + (off ^ ((off >> 3) & 0x70u)),
                          g_wh + (size_t)r*KK + kcn*64 + u*8);
            }
            asm volatile("cp.async.commit_group;" ::: "memory");
            if ((kcn & 3) == 0) COORDS(kcn >> 2);
            cbj = (kcn & 3)*64 + jj*8;
            LDG4(cbj, o1, d1x, d1y);     // pixel1 corners in flight
        }

        MMA_HALF(0)          // hides pixel1 LDG latency

        if (more) {
            BLEND_STS(AT_w, q1, w1x, w1y);
            LDG4(cbj, o2, d2x, d2y);     // pixel2 corners in flight
        }

        MMA_HALF(2)          // hides pixel2 LDG latency

        if (more) {
            BLEND_STS(AT_w, q1 + 32, w2x, w2y);
        }
    }

    // ---- epilogue: stage 256 o x 64 px through smem (stride 68) ----
    __syncthreads();
    float* ep = (float*)sm;
    const int qrow = lane >> 2;
    const int qcol = (lane & 3) * 2;
#pragma unroll
    for (int mt = 0; mt < 2; ++mt) {
#pragma unroll
        for (int nn = 0; nn < 8; ++nn) {
            int ol = wn*64 + nn*8 + qcol;
            int pr = wm*32 + mt*16 + qrow;
            ep[ol*68 + pr]         = acc[mt][nn][0];
            ep[(ol+1)*68 + pr]     = acc[mt][nn][1];
            ep[ol*68 + pr + 8]     = acc[mt][nn][2];
            ep[(ol+1)*68 + pr + 8] = acc[mt][nn][3];
        }
    }
    __syncthreads();
#pragma unroll
    for (int i = 0; i < 16; ++i) {
        int o = i*16 + (tid >> 4);
        int q = tid & 15;
        float bv = __ldg(&bias[o]);
        const float* er = ep + o*68 + q*4;
        float4 v = make_float4(er[0]+bv, er[1]+bv, er[2]+bv, er[3]+bv);
        *(float4*)(out + ((size_t)(b*OO + o))*HWP + p0 + q*4) = v;
    }
}

extern "C" void kernel_launch(void* const* d_in, const int* in_sizes, int n_in,
                              void* d_out, int out_size) {
    const float* x    = (const float*)d_in[0];
    const float* w    = (const float*)d_in[1];
    const float* bias = (const float*)d_in[2];
    const float* spw  = (const float*)d_in[3];
    const float* spb  = (const float*)d_in[4];
    float* out = (float*)d_out;

    cudaFuncSetAttribute(k_main, cudaFuncAttributeMaxDynamicSharedMemorySize, SMEM_DYN);

    k_transpose<<<dim3(HWP/64, CC/64, BB), 256>>>(x);
    k_whalf   <<<(OO*KK)/256, 256>>>(w);
    k_spwt    <<<(2*9*256 + 255)/256, 256>>>(spw);
    k_spconv  <<<BB*(HH/16)*(WW/16), 256>>>(spb);
    k_main    <<<(BB*HWP)/MT, 256, SMEM_DYN>>>(bias, out);
}